// round 12
// baseline (speedup 1.0000x reference)
#include <cuda_runtime.h>
#include <cstdint>

// ============================================================================
// OneHotEncoding — single kernel, zero grid barriers, block-local argmin.
//
// R11 lesson: the stream was latency-bound with ILP=1 — one point per thread
// per tile means one serial LDS->ALU->LDS->FMA->LDS chain (~200cy) per warp
// issue slot; occupancy couldn't hide it (R8). Fix: 3 points per thread per
// tile (independent chains), 2 CTAs/SM, warp-strided assignment so LDS stays
// conflict-free and out STG.128 becomes lane-contiguous.
//
// Output layout (float32):
//   [0, 4L)            input_tensor: per point (x, y, z, one_hot)
//   [4L, 4L+3B)        closest_points [B,3]
//   [4L+3B, 4L+4B)     min_index as float [B]
//
// Merge key: ~((u64)d2bits<<32 | idx), combined with max.
//   - zero-initialized .bss g_best IS the identity (no init pass)
//   - max of complement == min (d2, idx) => first-index tie-break
//   - probe seed ~(probe_d2<<32 | 0xFFFFFFFF) is provably below the true
//     winner's key (true d2 <= probe d2; real idx < 0xFFFFFFFF): filters only.
//   - finalize resets g_best/g_done to 0 => graph-replay deterministic.
//
// Candidate table: receiver r's box [r-UB, r+UB]^3 (UB = exact distance to a
// real sampled point; identical in every block) covers r's true NN. Cells
// with >KCAP receivers get sentinel 255 => brute-force all B there.
// Unconditionally correct.
// ============================================================================

#define GC       16
#define CELLS    (GC * GC * GC)        // 4096
#define MAXB     128
#define GRID     304                   // 2 CTAs/SM
#define THREADS  512
#define NWARP    (THREADS / 32)        // 16
#define KCAP     5                     // candidate list slots per cell
#define PROBE_N  512                   // sample points for UB probe
#define TILE     1536                  // points per tile (3 per thread)

__device__ unsigned long long g_best[MAXB];   // complemented keys; 0 = identity
__device__ unsigned int       g_done;         // zero-init; self-resetting

__device__ __forceinline__ int cell_of(float x) {
    int c = __float2int_rd(x * (float)GC);
    c = c < 0 ? 0 : c;
    return c > GC - 1 ? GC - 1 : c;
}

// ---------------------------------------------------------------------------
__global__ void __launch_bounds__(THREADS, 2)
fused_kernel(const float* __restrict__ pts, const float* __restrict__ recv,
             float* __restrict__ out, int L, int B)
{
    const int tid  = threadIdx.x;
    const int lane = tid & 31;
    const int wid  = tid >> 5;
    const int bid  = blockIdx.x;

    __shared__ float srx[MAXB], sry[MAXB], srz[MAXB];
    __shared__ float s_ub[MAXB];                       // probe min d2 per recv
    __shared__ unsigned long long s_best[MAXB];        // block-local keys
    __shared__ unsigned char s_list[CELLS * KCAP];     // 20 KB
    __shared__ unsigned char s_cnt[CELLS];             // 4 KB (255 = overflow)
    // scratch: probe SoA (6KB) -> cnt32 (16KB) -> point tile (18KB)
    __shared__ __align__(16) float s_scratch[3 * TILE];   // 18 KB

    // ---- stage receivers ----
    if (tid < B) {
        srx[tid] = recv[3 * tid + 0];
        sry[tid] = recv[3 * tid + 1];
        srz[tid] = recv[3 * tid + 2];
    }

    // ---- stage probe samples AoS into scratch (1536 floats) ----
    const int n = (L < PROBE_N) ? L : PROBE_N;
#pragma unroll
    for (int j = 0; j < 3; ++j) {
        int e = tid + j * THREADS;                 // [0, 1536)
        s_scratch[e] = (e < n * 3) ? pts[e] : 1.0e30f;
    }
    __syncthreads();

    // ---- UB probe: warp wid owns receivers [8*wid, 8*wid+8) ----
    {
        const int rbase = wid * 8;
        float rx[8], ry[8], rz[8], bd[8];
#pragma unroll
        for (int k = 0; k < 8; ++k) {
            int rb = rbase + k;
            rx[k] = (rb < B) ? srx[rb] : 0.f;
            ry[k] = (rb < B) ? sry[rb] : 0.f;
            rz[k] = (rb < B) ? srz[rb] : 0.f;
            bd[k] = 3.4e38f;
        }
#pragma unroll 4
        for (int j = 0; j < PROBE_N / 32; ++j) {
            int i = lane + 32 * j;
            float px = s_scratch[3 * i + 0];       // stride-3: conflict-free
            float py = s_scratch[3 * i + 1];
            float pz = s_scratch[3 * i + 2];
#pragma unroll
            for (int k = 0; k < 8; ++k) {
                float dx = px - rx[k];
                float dy = py - ry[k];
                float dz = pz - rz[k];
                float d2 = dx * dx + dy * dy + dz * dz;
                bd[k] = fminf(bd[k], d2);
            }
        }
#pragma unroll
        for (int k = 0; k < 8; ++k) {
#pragma unroll
            for (int m = 16; m > 0; m >>= 1)
                bd[k] = fminf(bd[k], __shfl_xor_sync(0xffffffffu, bd[k], m));
            if (lane == 0 && (rbase + k) < B) {
                s_ub[rbase + k] = bd[k];
                // seed: <= true winner's key (d2 >= true d2, idx field maximal)
                s_best[rbase + k] =
                    ~((((unsigned long long)__float_as_uint(bd[k])) << 32) |
                      0xFFFFFFFFull);
            }
        }
    }
    __syncthreads();

    // ---- zero cnt32 (reuses scratch: 16 KB of the 18 KB) ----
    unsigned int* cnt32 = reinterpret_cast<unsigned int*>(s_scratch);
#pragma unroll
    for (int j = 0; j < CELLS / THREADS; ++j) cnt32[tid + j * THREADS] = 0u;
    __syncthreads();

    // ---- build candidate lists (receiver-major, smem atomics) ----
    if (tid < B) {
        float ub = sqrtf(s_ub[tid]) * 1.0001f + 1e-7f;   // ulp guard
        float rx = srx[tid], ry = sry[tid], rz = srz[tid];
        int lx = cell_of(rx - ub), hx = cell_of(rx + ub);
        int ly = cell_of(ry - ub), hy = cell_of(ry + ub);
        int lz = cell_of(rz - ub), hz = cell_of(rz + ub);
        for (int zz = lz; zz <= hz; ++zz)
            for (int yy = ly; yy <= hy; ++yy)
                for (int xx = lx; xx <= hx; ++xx) {
                    int c = (zz * GC + yy) * GC + xx;
                    unsigned int pos = atomicAdd(&cnt32[c], 1u);
                    if (pos < KCAP) s_list[c * KCAP + pos] = (unsigned char)tid;
                }
    }
    __syncthreads();

    // ---- compact counts to u8 with overflow sentinel ----
#pragma unroll
    for (int j = 0; j < CELLS / THREADS; ++j) {
        int c = tid + j * THREADS;
        unsigned int v = cnt32[c];
        s_cnt[c] = (v > KCAP) ? (unsigned char)255 : (unsigned char)v;
    }
    __syncthreads();

    // ---- streaming pass: smem tiles, 3 points/thread (ILP=3) ----
    const int nTiles = (L + TILE - 1) / TILE;
    const int L3 = L * 3;

    for (int tile = bid; tile < nTiles; tile += GRID) {
        const int base  = tile * TILE;
        const int base3 = base * 3;
        __syncthreads();                 // previous tile fully consumed

        // stage tile (coalesced; float4 fast path covers 4608 floats)
        if (base3 + 3 * TILE <= L3) {
#pragma unroll
            for (int j = 0; j < 3; ++j) {
                int idx = tid + j * THREADS;       // [0, 1536) float4 slots
                if (idx < (3 * TILE) / 4)
                    reinterpret_cast<float4*>(s_scratch)[idx] =
                        reinterpret_cast<const float4*>(pts + base3)[idx];
            }
        } else {
#pragma unroll
            for (int j = 0; j < 9; ++j) {
                int e  = tid + j * THREADS;
                if (e < 3 * TILE) {
                    int ge = base3 + e;
                    s_scratch[e] = (ge < L3) ? pts[ge] : 2.0f;  // pad
                }
            }
        }
        __syncthreads();

        // warp wid owns tile-local points [96*wid, 96*wid+96), 3 chunks of 32
        float x[3], y[3], z[3];
        int   pp[3];
#pragma unroll
        for (int j = 0; j < 3; ++j) {
            int loc = 96 * wid + 32 * j + lane;
            pp[j] = base + loc;
            x[j] = s_scratch[3 * loc + 0];         // stride-3: conflict-free
            y[j] = s_scratch[3 * loc + 1];
            z[j] = s_scratch[3 * loc + 2];
        }
#pragma unroll
        for (int j = 0; j < 3; ++j) {
            if (pp[j] < L) {
                // lane-contiguous STG.128 (4 lines per instruction)
                *reinterpret_cast<float4*>(out + 4 * (size_t)pp[j]) =
                    make_float4(x[j], y[j], z[j], 0.0f);
            }
        }
        // candidate evaluation: 3 independent chains
        int  cc[3];
        unsigned int cn[3];
#pragma unroll
        for (int j = 0; j < 3; ++j) {
            cc[j] = (cell_of(z[j]) * GC + cell_of(y[j])) * GC + cell_of(x[j]);
            cn[j] = (pp[j] < L) ? (unsigned int)s_cnt[cc[j]] : 0u;
        }
#pragma unroll
        for (int j = 0; j < 3; ++j) {
            if (cn[j]) {
                int  lim = (cn[j] == 255u) ? B : (int)cn[j];
                bool all = (cn[j] == 255u);
                for (int k = 0; k < lim; ++k) {
                    int r = all ? k : (int)s_list[cc[j] * KCAP + k];
                    float dx = x[j] - srx[r];
                    float dy = y[j] - sry[r];
                    float dz = z[j] - srz[r];
                    float d2 = dx * dx + dy * dy + dz * dz;
                    unsigned long long key =
                        ~((((unsigned long long)__float_as_uint(d2)) << 32) |
                          (unsigned long long)(unsigned int)pp[j]);
                    // LDS guard block-coherent; smem atomic authoritative
                    if (key > s_best[r]) atomicMax(&s_best[r], key);
                }
            }
        }
    }
    __syncthreads();   // all smem atomics visible (also for zero-tile blocks)

    // ---- one global merge per block (<=128 atomics) ----
    if (tid < B) atomicMax(&g_best[tid], s_best[tid]);

    // ---- last-finishing block finalizes ----
    __threadfence();
    __syncthreads();
    __shared__ bool is_last;
    if (tid == 0) is_last = (atomicAdd(&g_done, 1u) == GRID - 1);
    __syncthreads();
    if (!is_last) return;

    if (tid < B) {
        // authoritative read (atomicMax with identity 0 leaves value intact)
        unsigned long long key = atomicMax(&g_best[tid], 0ull);
        unsigned int idx = ~((unsigned int)(key & 0xffffffffull));
        float* cp = out + 4 * (size_t)L;
        cp[3 * tid + 0] = pts[3 * idx + 0];
        cp[3 * tid + 1] = pts[3 * idx + 1];
        cp[3 * tid + 2] = pts[3 * idx + 2];
        out[4 * (size_t)L + 3 * B + tid] = (float)idx;   // min_index as float
        out[4 * (size_t)idx + 3] = 1.0f;                 // one-hot scatter
        g_best[tid] = 0ull;                              // reset for next replay
    }
    if (tid == 0) {
        if (B > 1) out[3] = 1.0f;        // reference quirk: index 0 also set
        g_done = 0u;                     // reset for next replay
    }
}

// ---------------------------------------------------------------------------
extern "C" void kernel_launch(void* const* d_in, const int* in_sizes, int n_in,
                              void* d_out, int out_size)
{
    const float* pts  = (const float*)d_in[0];   // mesh_3D flattened [L,3]
    const float* recv = (const float*)d_in[1];   // receiver_pos [B,3]
    float* out = (float*)d_out;

    int L = in_sizes[0] / 3;   // 1,000,000
    int B = in_sizes[1] / 3;   // 128

    fused_kernel<<<GRID, THREADS>>>(pts, recv, out, L, B);
}